// round 3
// baseline (speedup 1.0000x reference)
#include <cuda_runtime.h>

// AttentionAutoInt: out = relu(x@Wr + softmax((x@Wq)(x@Wk)^T) @ (x@Wv))
// B=8192, M=64, D=DP=128, fp32.
//
// Round-0 baseline: fully fused, one CTA per batch, fp32 CUDA-core math.
// smem: x tile + staged weight + padded q/k/v tiles + scores = 211 KB, 1 CTA/SM.

static constexpr int Mdim = 64;
static constexpr int Ddim = 128;
static constexpr int QS   = 132;   // padded row stride (floats) for q/k/v: kills
                                   // the 32-way LDS bank conflict in the scores
                                   // phase (132 mod 32 = 4 -> worst case 4-way)
static constexpr int NTHREADS = 512;

static constexpr int OFF_XS = 0;                    // x   [64][128]
static constexpr int OFF_WS = OFF_XS + Mdim * Ddim; // W   [128][128] (staged per projection)
static constexpr int OFF_QS = OFF_WS + Ddim * Ddim; // q   [64][132]
static constexpr int OFF_KS = OFF_QS + Mdim * QS;   // k   [64][132]
static constexpr int OFF_VS = OFF_KS + Mdim * QS;   // v   [64][132]
static constexpr int OFF_SS = OFF_VS + Mdim * QS;   // s   [64][64]
static constexpr int SMEM_FLOATS = OFF_SS + Mdim * Mdim;
static constexpr int SMEM_BYTES  = SMEM_FLOATS * (int)sizeof(float); // 216064

// Stage a 128x128 fp32 weight matrix from gmem (L2-resident) into smem.
__device__ __forceinline__ void stage_weight(const float* __restrict__ g,
                                             float* __restrict__ ws, int tid) {
    const float4* g4 = reinterpret_cast<const float4*>(g);
    float4* w4 = reinterpret_cast<float4*>(ws);
#pragma unroll
    for (int i = 0; i < 8; i++) w4[tid + i * NTHREADS] = g4[tid + i * NTHREADS];
}

// dst[m][e] = sum_d xs[m][d] * ws[d][e].
// Warp w owns rows m0..m0+3; lane owns 4 consecutive e-columns (float4).
// Per d: 1 LDS.128 (weights, conflict-free) + 4 LDS.32 (x, broadcast) + 16 FFMA.
__device__ __forceinline__ void gemm_xw(const float* __restrict__ xs,
                                        const float* __restrict__ ws,
                                        float* __restrict__ dst,
                                        int w, int ln) {
    const int m0 = w * 4;
    float4 a0 = make_float4(0.f, 0.f, 0.f, 0.f), a1 = a0, a2 = a0, a3 = a0;
#pragma unroll 4
    for (int d = 0; d < Ddim; d++) {
        const float4 wv = *reinterpret_cast<const float4*>(ws + d * Ddim + ln * 4);
        const float x0 = xs[(m0 + 0) * Ddim + d];
        const float x1 = xs[(m0 + 1) * Ddim + d];
        const float x2 = xs[(m0 + 2) * Ddim + d];
        const float x3 = xs[(m0 + 3) * Ddim + d];
        a0.x = fmaf(x0, wv.x, a0.x); a0.y = fmaf(x0, wv.y, a0.y);
        a0.z = fmaf(x0, wv.z, a0.z); a0.w = fmaf(x0, wv.w, a0.w);
        a1.x = fmaf(x1, wv.x, a1.x); a1.y = fmaf(x1, wv.y, a1.y);
        a1.z = fmaf(x1, wv.z, a1.z); a1.w = fmaf(x1, wv.w, a1.w);
        a2.x = fmaf(x2, wv.x, a2.x); a2.y = fmaf(x2, wv.y, a2.y);
        a2.z = fmaf(x2, wv.z, a2.z); a2.w = fmaf(x2, wv.w, a2.w);
        a3.x = fmaf(x3, wv.x, a3.x); a3.y = fmaf(x3, wv.y, a3.y);
        a3.z = fmaf(x3, wv.z, a3.z); a3.w = fmaf(x3, wv.w, a3.w);
    }
    *reinterpret_cast<float4*>(dst + (m0 + 0) * QS + ln * 4) = a0;
    *reinterpret_cast<float4*>(dst + (m0 + 1) * QS + ln * 4) = a1;
    *reinterpret_cast<float4*>(dst + (m0 + 2) * QS + ln * 4) = a2;
    *reinterpret_cast<float4*>(dst + (m0 + 3) * QS + ln * 4) = a3;
}

__global__ __launch_bounds__(NTHREADS, 1)
void autoint_kernel(const float* __restrict__ x,
                    const float* __restrict__ Wq, const float* __restrict__ Wk,
                    const float* __restrict__ Wv, const float* __restrict__ Wr,
                    float* __restrict__ out) {
    extern __shared__ float sm[];
    float* xs = sm + OFF_XS;
    float* ws = sm + OFF_WS;
    float* qs = sm + OFF_QS;
    float* ks = sm + OFF_KS;
    float* vs = sm + OFF_VS;
    float* ss = sm + OFF_SS;

    const int b   = blockIdx.x;
    const int tid = threadIdx.x;
    const int w   = tid >> 5;
    const int ln  = tid & 31;

    // ---- P1: load x[b] (64x128) ----
    {
        const float4* gx = reinterpret_cast<const float4*>(x + (size_t)b * Mdim * Ddim);
        float4* xs4 = reinterpret_cast<float4*>(xs);
#pragma unroll
        for (int i = 0; i < 4; i++) xs4[tid + i * NTHREADS] = gx[tid + i * NTHREADS];
    }
    __syncthreads();

    // ---- P2: q, k, v projections (weight staged through smem) ----
    stage_weight(Wq, ws, tid); __syncthreads();
    gemm_xw(xs, ws, qs, w, ln); __syncthreads();
    stage_weight(Wk, ws, tid); __syncthreads();
    gemm_xw(xs, ws, ks, w, ln); __syncthreads();
    stage_weight(Wv, ws, tid); __syncthreads();
    gemm_xw(xs, ws, vs, w, ln); __syncthreads();

    // ---- P3: scores s[m][n] = q[m,:] . k[n,:]  (warp: 4 m-rows; lane: n, n+32) ----
    {
        const int m0 = w * 4;
        float acc0[4] = {0.f, 0.f, 0.f, 0.f};
        float acc1[4] = {0.f, 0.f, 0.f, 0.f};
#pragma unroll 2
        for (int d = 0; d < Ddim; d += 4) {
            const float4 k0 = *reinterpret_cast<const float4*>(ks + ln * QS + d);
            const float4 k1 = *reinterpret_cast<const float4*>(ks + (ln + 32) * QS + d);
#pragma unroll
            for (int mi = 0; mi < 4; mi++) {
                const float4 qv = *reinterpret_cast<const float4*>(qs + (m0 + mi) * QS + d);
                acc0[mi] = fmaf(qv.x, k0.x, fmaf(qv.y, k0.y, fmaf(qv.z, k0.z, fmaf(qv.w, k0.w, acc0[mi]))));
                acc1[mi] = fmaf(qv.x, k1.x, fmaf(qv.y, k1.y, fmaf(qv.z, k1.z, fmaf(qv.w, k1.w, acc1[mi]))));
            }
        }
#pragma unroll
        for (int mi = 0; mi < 4; mi++) {
            ss[(m0 + mi) * Mdim + ln]      = acc0[mi];
            ss[(m0 + mi) * Mdim + ln + 32] = acc1[mi];
        }
    }
    __syncthreads();

    // ---- P4: softmax over n (each warp: 4 rows) ----
    {
        const int m0 = w * 4;
#pragma unroll
        for (int mi = 0; mi < 4; mi++) {
            const int m = m0 + mi;
            float s0 = ss[m * Mdim + ln];
            float s1 = ss[m * Mdim + ln + 32];
            float mx = fmaxf(s0, s1);
#pragma unroll
            for (int o = 16; o > 0; o >>= 1) mx = fmaxf(mx, __shfl_xor_sync(0xffffffffu, mx, o));
            const float e0 = __expf(s0 - mx);
            const float e1 = __expf(s1 - mx);
            float sum = e0 + e1;
#pragma unroll
            for (int o = 16; o > 0; o >>= 1) sum += __shfl_xor_sync(0xffffffffu, sum, o);
            const float inv = 1.0f / sum;
            ss[m * Mdim + ln]      = e0 * inv;
            ss[m * Mdim + ln + 32] = e1 * inv;
        }
    }
    __syncthreads();

    // ---- P5: stage Wr (r projection fused into epilogue) ----
    stage_weight(Wr, ws, tid);
    __syncthreads();

    // ---- P6: out[m][e] = relu( x@Wr + alphas @ v ) ----
    {
        const int m0 = w * 4;
        float4 a0 = make_float4(0.f, 0.f, 0.f, 0.f), a1 = a0, a2 = a0, a3 = a0;

        // r part: same microtile as gemm_xw
#pragma unroll 4
        for (int d = 0; d < Ddim; d++) {
            const float4 wv = *reinterpret_cast<const float4*>(ws + d * Ddim + ln * 4);
            const float x0 = xs[(m0 + 0) * Ddim + d];
            const float x1 = xs[(m0 + 1) * Ddim + d];
            const float x2 = xs[(m0 + 2) * Ddim + d];
            const float x3 = xs[(m0 + 3) * Ddim + d];
            a0.x = fmaf(x0, wv.x, a0.x); a0.y = fmaf(x0, wv.y, a0.y);
            a0.z = fmaf(x0, wv.z, a0.z); a0.w = fmaf(x0, wv.w, a0.w);
            a1.x = fmaf(x1, wv.x, a1.x); a1.y = fmaf(x1, wv.y, a1.y);
            a1.z = fmaf(x1, wv.z, a1.z); a1.w = fmaf(x1, wv.w, a1.w);
            a2.x = fmaf(x2, wv.x, a2.x); a2.y = fmaf(x2, wv.y, a2.y);
            a2.z = fmaf(x2, wv.z, a2.z); a2.w = fmaf(x2, wv.w, a2.w);
            a3.x = fmaf(x3, wv.x, a3.x); a3.y = fmaf(x3, wv.y, a3.y);
            a3.z = fmaf(x3, wv.z, a3.z); a3.w = fmaf(x3, wv.w, a3.w);
        }

        // attention part: acc += alphas[m][n] * v[n][e]
#pragma unroll 4
        for (int n = 0; n < Mdim; n++) {
            const float4 vv = *reinterpret_cast<const float4*>(vs + n * QS + ln * 4);
            const float p0 = ss[(m0 + 0) * Mdim + n];
            const float p1 = ss[(m0 + 1) * Mdim + n];
            const float p2 = ss[(m0 + 2) * Mdim + n];
            const float p3 = ss[(m0 + 3) * Mdim + n];
            a0.x = fmaf(p0, vv.x, a0.x); a0.y = fmaf(p0, vv.y, a0.y);
            a0.z = fmaf(p0, vv.z, a0.z); a0.w = fmaf(p0, vv.w, a0.w);
            a1.x = fmaf(p1, vv.x, a1.x); a1.y = fmaf(p1, vv.y, a1.y);
            a1.z = fmaf(p1, vv.z, a1.z); a1.w = fmaf(p1, vv.w, a1.w);
            a2.x = fmaf(p2, vv.x, a2.x); a2.y = fmaf(p2, vv.y, a2.y);
            a2.z = fmaf(p2, vv.z, a2.z); a2.w = fmaf(p2, vv.w, a2.w);
            a3.x = fmaf(p3, vv.x, a3.x); a3.y = fmaf(p3, vv.y, a3.y);
            a3.z = fmaf(p3, vv.z, a3.z); a3.w = fmaf(p3, vv.w, a3.w);
        }

        float4* out4 = reinterpret_cast<float4*>(out + (size_t)b * Mdim * Ddim);
        float4 r0, r1, r2, r3;
        r0.x = fmaxf(a0.x, 0.f); r0.y = fmaxf(a0.y, 0.f); r0.z = fmaxf(a0.z, 0.f); r0.w = fmaxf(a0.w, 0.f);
        r1.x = fmaxf(a1.x, 0.f); r1.y = fmaxf(a1.y, 0.f); r1.z = fmaxf(a1.z, 0.f); r1.w = fmaxf(a1.w, 0.f);
        r2.x = fmaxf(a2.x, 0.f); r2.y = fmaxf(a2.y, 0.f); r2.z = fmaxf(a2.z, 0.f); r2.w = fmaxf(a2.w, 0.f);
        r3.x = fmaxf(a3.x, 0.f); r3.y = fmaxf(a3.y, 0.f); r3.z = fmaxf(a3.z, 0.f); r3.w = fmaxf(a3.w, 0.f);
        out4[(m0 + 0) * 32 + ln] = r0;
        out4[(m0 + 1) * 32 + ln] = r1;
        out4[(m0 + 2) * 32 + ln] = r2;
        out4[(m0 + 3) * 32 + ln] = r3;
    }
}

extern "C" void kernel_launch(void* const* d_in, const int* in_sizes, int n_in,
                              void* d_out, int out_size) {
    const float* x  = (const float*)d_in[0];
    const float* Wq = (const float*)d_in[1];
    const float* Wk = (const float*)d_in[2];
    const float* Wv = (const float*)d_in[3];
    const float* Wr = (const float*)d_in[4];
    float* out = (float*)d_out;

    cudaFuncSetAttribute(autoint_kernel,
                         cudaFuncAttributeMaxDynamicSharedMemorySize, SMEM_BYTES);
    autoint_kernel<<<8192, NTHREADS, SMEM_BYTES>>>(x, Wq, Wk, Wv, Wr, out);
}

// round 4
// speedup vs baseline: 1.0017x; 1.0017x over previous
#include <cuda_runtime.h>

// AttentionAutoInt: out = relu(x@Wr + softmax((x@Wq)(x@Wk)^T) @ (x@Wv))
// B=8192, M=64, D=DP=128, fp32.
//
// Round-0 baseline: fully fused, one CTA per batch, fp32 CUDA-core math.
// smem: x tile + staged weight + padded q/k/v tiles + scores = 211 KB, 1 CTA/SM.

static constexpr int Mdim = 64;
static constexpr int Ddim = 128;
static constexpr int QS   = 132;   // padded row stride (floats) for q/k/v: kills
                                   // the 32-way LDS bank conflict in the scores
                                   // phase (132 mod 32 = 4 -> worst case 4-way)
static constexpr int NTHREADS = 512;

static constexpr int OFF_XS = 0;                    // x   [64][128]
static constexpr int OFF_WS = OFF_XS + Mdim * Ddim; // W   [128][128] (staged per projection)
static constexpr int OFF_QS = OFF_WS + Ddim * Ddim; // q   [64][132]
static constexpr int OFF_KS = OFF_QS + Mdim * QS;   // k   [64][132]
static constexpr int OFF_VS = OFF_KS + Mdim * QS;   // v   [64][132]
static constexpr int OFF_SS = OFF_VS + Mdim * QS;   // s   [64][64]
static constexpr int SMEM_FLOATS = OFF_SS + Mdim * Mdim;
static constexpr int SMEM_BYTES  = SMEM_FLOATS * (int)sizeof(float); // 216064

// Stage a 128x128 fp32 weight matrix from gmem (L2-resident) into smem.
__device__ __forceinline__ void stage_weight(const float* __restrict__ g,
                                             float* __restrict__ ws, int tid) {
    const float4* g4 = reinterpret_cast<const float4*>(g);
    float4* w4 = reinterpret_cast<float4*>(ws);
#pragma unroll
    for (int i = 0; i < 8; i++) w4[tid + i * NTHREADS] = g4[tid + i * NTHREADS];
}

// dst[m][e] = sum_d xs[m][d] * ws[d][e].
// Warp w owns rows m0..m0+3; lane owns 4 consecutive e-columns (float4).
// Per d: 1 LDS.128 (weights, conflict-free) + 4 LDS.32 (x, broadcast) + 16 FFMA.
__device__ __forceinline__ void gemm_xw(const float* __restrict__ xs,
                                        const float* __restrict__ ws,
                                        float* __restrict__ dst,
                                        int w, int ln) {
    const int m0 = w * 4;
    float4 a0 = make_float4(0.f, 0.f, 0.f, 0.f), a1 = a0, a2 = a0, a3 = a0;
#pragma unroll 4
    for (int d = 0; d < Ddim; d++) {
        const float4 wv = *reinterpret_cast<const float4*>(ws + d * Ddim + ln * 4);
        const float x0 = xs[(m0 + 0) * Ddim + d];
        const float x1 = xs[(m0 + 1) * Ddim + d];
        const float x2 = xs[(m0 + 2) * Ddim + d];
        const float x3 = xs[(m0 + 3) * Ddim + d];
        a0.x = fmaf(x0, wv.x, a0.x); a0.y = fmaf(x0, wv.y, a0.y);
        a0.z = fmaf(x0, wv.z, a0.z); a0.w = fmaf(x0, wv.w, a0.w);
        a1.x = fmaf(x1, wv.x, a1.x); a1.y = fmaf(x1, wv.y, a1.y);
        a1.z = fmaf(x1, wv.z, a1.z); a1.w = fmaf(x1, wv.w, a1.w);
        a2.x = fmaf(x2, wv.x, a2.x); a2.y = fmaf(x2, wv.y, a2.y);
        a2.z = fmaf(x2, wv.z, a2.z); a2.w = fmaf(x2, wv.w, a2.w);
        a3.x = fmaf(x3, wv.x, a3.x); a3.y = fmaf(x3, wv.y, a3.y);
        a3.z = fmaf(x3, wv.z, a3.z); a3.w = fmaf(x3, wv.w, a3.w);
    }
    *reinterpret_cast<float4*>(dst + (m0 + 0) * QS + ln * 4) = a0;
    *reinterpret_cast<float4*>(dst + (m0 + 1) * QS + ln * 4) = a1;
    *reinterpret_cast<float4*>(dst + (m0 + 2) * QS + ln * 4) = a2;
    *reinterpret_cast<float4*>(dst + (m0 + 3) * QS + ln * 4) = a3;
}

__global__ __launch_bounds__(NTHREADS, 1)
void autoint_kernel(const float* __restrict__ x,
                    const float* __restrict__ Wq, const float* __restrict__ Wk,
                    const float* __restrict__ Wv, const float* __restrict__ Wr,
                    float* __restrict__ out) {
    extern __shared__ float sm[];
    float* xs = sm + OFF_XS;
    float* ws = sm + OFF_WS;
    float* qs = sm + OFF_QS;
    float* ks = sm + OFF_KS;
    float* vs = sm + OFF_VS;
    float* ss = sm + OFF_SS;

    const int b   = blockIdx.x;
    const int tid = threadIdx.x;
    const int w   = tid >> 5;
    const int ln  = tid & 31;

    // ---- P1: load x[b] (64x128) ----
    {
        const float4* gx = reinterpret_cast<const float4*>(x + (size_t)b * Mdim * Ddim);
        float4* xs4 = reinterpret_cast<float4*>(xs);
#pragma unroll
        for (int i = 0; i < 4; i++) xs4[tid + i * NTHREADS] = gx[tid + i * NTHREADS];
    }
    __syncthreads();

    // ---- P2: q, k, v projections (weight staged through smem) ----
    stage_weight(Wq, ws, tid); __syncthreads();
    gemm_xw(xs, ws, qs, w, ln); __syncthreads();
    stage_weight(Wk, ws, tid); __syncthreads();
    gemm_xw(xs, ws, ks, w, ln); __syncthreads();
    stage_weight(Wv, ws, tid); __syncthreads();
    gemm_xw(xs, ws, vs, w, ln); __syncthreads();

    // ---- P3: scores s[m][n] = q[m,:] . k[n,:]  (warp: 4 m-rows; lane: n, n+32) ----
    {
        const int m0 = w * 4;
        float acc0[4] = {0.f, 0.f, 0.f, 0.f};
        float acc1[4] = {0.f, 0.f, 0.f, 0.f};
#pragma unroll 2
        for (int d = 0; d < Ddim; d += 4) {
            const float4 k0 = *reinterpret_cast<const float4*>(ks + ln * QS + d);
            const float4 k1 = *reinterpret_cast<const float4*>(ks + (ln + 32) * QS + d);
#pragma unroll
            for (int mi = 0; mi < 4; mi++) {
                const float4 qv = *reinterpret_cast<const float4*>(qs + (m0 + mi) * QS + d);
                acc0[mi] = fmaf(qv.x, k0.x, fmaf(qv.y, k0.y, fmaf(qv.z, k0.z, fmaf(qv.w, k0.w, acc0[mi]))));
                acc1[mi] = fmaf(qv.x, k1.x, fmaf(qv.y, k1.y, fmaf(qv.z, k1.z, fmaf(qv.w, k1.w, acc1[mi]))));
            }
        }
#pragma unroll
        for (int mi = 0; mi < 4; mi++) {
            ss[(m0 + mi) * Mdim + ln]      = acc0[mi];
            ss[(m0 + mi) * Mdim + ln + 32] = acc1[mi];
        }
    }
    __syncthreads();

    // ---- P4: softmax over n (each warp: 4 rows) ----
    {
        const int m0 = w * 4;
#pragma unroll
        for (int mi = 0; mi < 4; mi++) {
            const int m = m0 + mi;
            float s0 = ss[m * Mdim + ln];
            float s1 = ss[m * Mdim + ln + 32];
            float mx = fmaxf(s0, s1);
#pragma unroll
            for (int o = 16; o > 0; o >>= 1) mx = fmaxf(mx, __shfl_xor_sync(0xffffffffu, mx, o));
            const float e0 = __expf(s0 - mx);
            const float e1 = __expf(s1 - mx);
            float sum = e0 + e1;
#pragma unroll
            for (int o = 16; o > 0; o >>= 1) sum += __shfl_xor_sync(0xffffffffu, sum, o);
            const float inv = 1.0f / sum;
            ss[m * Mdim + ln]      = e0 * inv;
            ss[m * Mdim + ln + 32] = e1 * inv;
        }
    }
    __syncthreads();

    // ---- P5: stage Wr (r projection fused into epilogue) ----
    stage_weight(Wr, ws, tid);
    __syncthreads();

    // ---- P6: out[m][e] = relu( x@Wr + alphas @ v ) ----
    {
        const int m0 = w * 4;
        float4 a0 = make_float4(0.f, 0.f, 0.f, 0.f), a1 = a0, a2 = a0, a3 = a0;

        // r part: same microtile as gemm_xw
#pragma unroll 4
        for (int d = 0; d < Ddim; d++) {
            const float4 wv = *reinterpret_cast<const float4*>(ws + d * Ddim + ln * 4);
            const float x0 = xs[(m0 + 0) * Ddim + d];
            const float x1 = xs[(m0 + 1) * Ddim + d];
            const float x2 = xs[(m0 + 2) * Ddim + d];
            const float x3 = xs[(m0 + 3) * Ddim + d];
            a0.x = fmaf(x0, wv.x, a0.x); a0.y = fmaf(x0, wv.y, a0.y);
            a0.z = fmaf(x0, wv.z, a0.z); a0.w = fmaf(x0, wv.w, a0.w);
            a1.x = fmaf(x1, wv.x, a1.x); a1.y = fmaf(x1, wv.y, a1.y);
            a1.z = fmaf(x1, wv.z, a1.z); a1.w = fmaf(x1, wv.w, a1.w);
            a2.x = fmaf(x2, wv.x, a2.x); a2.y = fmaf(x2, wv.y, a2.y);
            a2.z = fmaf(x2, wv.z, a2.z); a2.w = fmaf(x2, wv.w, a2.w);
            a3.x = fmaf(x3, wv.x, a3.x); a3.y = fmaf(x3, wv.y, a3.y);
            a3.z = fmaf(x3, wv.z, a3.z); a3.w = fmaf(x3, wv.w, a3.w);
        }

        // attention part: acc += alphas[m][n] * v[n][e]
#pragma unroll 4
        for (int n = 0; n < Mdim; n++) {
            const float4 vv = *reinterpret_cast<const float4*>(vs + n * QS + ln * 4);
            const float p0 = ss[(m0 + 0) * Mdim + n];
            const float p1 = ss[(m0 + 1) * Mdim + n];
            const float p2 = ss[(m0 + 2) * Mdim + n];
            const float p3 = ss[(m0 + 3) * Mdim + n];
            a0.x = fmaf(p0, vv.x, a0.x); a0.y = fmaf(p0, vv.y, a0.y);
            a0.z = fmaf(p0, vv.z, a0.z); a0.w = fmaf(p0, vv.w, a0.w);
            a1.x = fmaf(p1, vv.x, a1.x); a1.y = fmaf(p1, vv.y, a1.y);
            a1.z = fmaf(p1, vv.z, a1.z); a1.w = fmaf(p1, vv.w, a1.w);
            a2.x = fmaf(p2, vv.x, a2.x); a2.y = fmaf(p2, vv.y, a2.y);
            a2.z = fmaf(p2, vv.z, a2.z); a2.w = fmaf(p2, vv.w, a2.w);
            a3.x = fmaf(p3, vv.x, a3.x); a3.y = fmaf(p3, vv.y, a3.y);
            a3.z = fmaf(p3, vv.z, a3.z); a3.w = fmaf(p3, vv.w, a3.w);
        }

        float4* out4 = reinterpret_cast<float4*>(out + (size_t)b * Mdim * Ddim);
        float4 r0, r1, r2, r3;
        r0.x = fmaxf(a0.x, 0.f); r0.y = fmaxf(a0.y, 0.f); r0.z = fmaxf(a0.z, 0.f); r0.w = fmaxf(a0.w, 0.f);
        r1.x = fmaxf(a1.x, 0.f); r1.y = fmaxf(a1.y, 0.f); r1.z = fmaxf(a1.z, 0.f); r1.w = fmaxf(a1.w, 0.f);
        r2.x = fmaxf(a2.x, 0.f); r2.y = fmaxf(a2.y, 0.f); r2.z = fmaxf(a2.z, 0.f); r2.w = fmaxf(a2.w, 0.f);
        r3.x = fmaxf(a3.x, 0.f); r3.y = fmaxf(a3.y, 0.f); r3.z = fmaxf(a3.z, 0.f); r3.w = fmaxf(a3.w, 0.f);
        out4[(m0 + 0) * 32 + ln] = r0;
        out4[(m0 + 1) * 32 + ln] = r1;
        out4[(m0 + 2) * 32 + ln] = r2;
        out4[(m0 + 3) * 32 + ln] = r3;
    }
}

extern "C" void kernel_launch(void* const* d_in, const int* in_sizes, int n_in,
                              void* d_out, int out_size) {
    const float* x  = (const float*)d_in[0];
    const float* Wq = (const float*)d_in[1];
    const float* Wk = (const float*)d_in[2];
    const float* Wv = (const float*)d_in[3];
    const float* Wr = (const float*)d_in[4];
    float* out = (float*)d_out;

    cudaFuncSetAttribute(autoint_kernel,
                         cudaFuncAttributeMaxDynamicSharedMemorySize, SMEM_BYTES);
    autoint_kernel<<<8192, NTHREADS, SMEM_BYTES>>>(x, Wq, Wk, Wv, Wr, out);
}

// round 6
// speedup vs baseline: 2.1622x; 2.1585x over previous
#include <cuda_runtime.h>
#include <cuda_bf16.h>
#include <mma.h>
#include <cstdint>

using namespace nvcuda;

#define DI __device__ __forceinline__

static constexpr int NT = 256;
static constexpr int SB = 136;   // bf16 tile stride (elems), 272B (mult of 16B)
static constexpr int SP = 72;    // P (alphas) stride
static constexpr int SF = 132;   // fp32 proj temp stride
static constexpr int SS = 68;    // fp32 scores temp stride

// ---- smem byte offsets ----
static constexpr int XHI = 0;                 // x hi   [64][SB] bf16 (17408 B)
static constexpr int XLO = 17408;             // x lo
static constexpr int WHI = 34816;             // W hi   [128][SB] bf16 (34816 B); aliases fp32 TMP
static constexpr int WLO = 69632;             // W lo
static constexpr int QHI = 104448;            // q hi   [64][SB]; later P hi [64][SP]
static constexpr int QLO = 121856;
static constexpr int KHI = 139264;
static constexpr int KLO = 156672;
static constexpr int VHI = 174080;
static constexpr int VLO = 191488;
static constexpr int SMEM_BYTES = 208896;     // 204 KB -> 1 CTA/SM

// prepped W^T (row = e, col = d), bf16 hi/lo
__device__ __align__(16) __nv_bfloat16 g_Whi[4][128 * 128];
__device__ __align__(16) __nv_bfloat16 g_Wlo[4][128 * 128];

DI unsigned pack2(__nv_bfloat16 a, __nv_bfloat16 b) {
    return (unsigned)__bfloat16_as_ushort(a) | ((unsigned)__bfloat16_as_ushort(b) << 16);
}
DI void split2(float v0, float v1, unsigned& h, unsigned& l) {
    __nv_bfloat16 h0 = __float2bfloat16_rn(v0), h1 = __float2bfloat16_rn(v1);
    __nv_bfloat16 l0 = __float2bfloat16_rn(v0 - __bfloat162float(h0));
    __nv_bfloat16 l1 = __float2bfloat16_rn(v1 - __bfloat162float(h1));
    h = pack2(h0, h1); l = pack2(l0, l1);
}

// ---------------------------------------------------------------- prep kernel
__global__ void prep_weights(const float* __restrict__ Wq, const float* __restrict__ Wk,
                             const float* __restrict__ Wv, const float* __restrict__ Wr) {
    const float* Ws[4] = {Wq, Wk, Wv, Wr};
    int i = blockIdx.x * 256 + threadIdx.x;          // 65536 threads
    int p = i >> 14, rem = i & 16383;
    int d = rem >> 7, e = rem & 127;
    float w = Ws[p][rem];
    __nv_bfloat16 hi = __float2bfloat16_rn(w);
    g_Whi[p][e * 128 + d] = hi;                      // transposed: [e][d]
    g_Wlo[p][e * 128 + d] = __float2bfloat16_rn(w - __bfloat162float(hi));
}

// ---------------------------------------------------------------- main kernel
using FA  = wmma::fragment<wmma::matrix_a, 16, 16, 16, __nv_bfloat16, wmma::row_major>;
using FBc = wmma::fragment<wmma::matrix_b, 16, 16, 16, __nv_bfloat16, wmma::col_major>;
using FBr = wmma::fragment<wmma::matrix_b, 16, 16, 16, __nv_bfloat16, wmma::row_major>;
using FC  = wmma::fragment<wmma::accumulator, 16, 16, 16, float>;

__global__ __launch_bounds__(NT, 1)
void autoint_hmma(const float* __restrict__ x, float* __restrict__ out) {
    extern __shared__ __align__(16) char sm[];
    const int b    = blockIdx.x;
    const int tid  = threadIdx.x;
    const int wid  = tid >> 5;

    const __nv_bfloat16* xhi = (const __nv_bfloat16*)(sm + XHI);
    const __nv_bfloat16* xlo = (const __nv_bfloat16*)(sm + XLO);
    const __nv_bfloat16* whi = (const __nv_bfloat16*)(sm + WHI);
    const __nv_bfloat16* wlo = (const __nv_bfloat16*)(sm + WLO);
    float* tmp = (float*)(sm + WHI);   // fp32 temp aliases W-hi buffer

    // ---- load x[b] (64x128 fp32) -> bf16 hi/lo tiles ----
    {
        const float4* gx = (const float4*)(x + (size_t)b * 8192);
#pragma unroll
        for (int i = 0; i < 8; i++) {
            int idx = tid + i * NT;
            int row = idx >> 5, c = (idx & 31) * 4;
            float4 f = gx[idx];
            unsigned h0, l0, h1, l1;
            split2(f.x, f.y, h0, l0);
            split2(f.z, f.w, h1, l1);
            *(uint2*)(sm + XHI + (row * SB + c) * 2) = make_uint2(h0, h1);
            *(uint2*)(sm + XLO + (row * SB + c) * 2) = make_uint2(l0, l1);
        }
    }

    // stage W^T hi+lo for projection p into WHI/WLO
    auto stage_W = [&](int p) {
        const uint4* gh = (const uint4*)g_Whi[p];
        const uint4* gl = (const uint4*)g_Wlo[p];
#pragma unroll
        for (int i = 0; i < 8; i++) {
            int idx = tid + i * NT;              // 2048 uint4 per matrix
            int e = idx >> 4, d8 = (idx & 15) * 8;
            *(uint4*)(sm + WHI + (e * SB + d8) * 2) = gh[idx];
            *(uint4*)(sm + WLO + (e * SB + d8) * 2) = gl[idx];
        }
    };

    // ---- projections q, k, v : acc = Xhi@Whi + Xhi@Wlo + Xlo@Whi ----
    const int DSTH[3] = {QHI, KHI, VHI};
    const int DSTL[3] = {QLO, KLO, VLO};
    const int m0 = 32 * (wid >> 2);      // warp: 2 m-tiles (rows m0, m0+16)
    const int n0 = 32 * (wid & 3);       //       2 n-tiles (cols n0, n0+16)

#pragma unroll 1
    for (int p = 0; p < 3; p++) {
        stage_W(p);
        __syncthreads();

        FC acc[2][2];
#pragma unroll
        for (int i = 0; i < 2; i++)
#pragma unroll
            for (int j = 0; j < 2; j++) wmma::fill_fragment(acc[i][j], 0.0f);

#pragma unroll 1
        for (int k = 0; k < 128; k += 16) {
            FA ah[2], al[2];
            FBc bh[2], bl[2];
#pragma unroll
            for (int i = 0; i < 2; i++) {
                wmma::load_matrix_sync(ah[i], xhi + (m0 + 16 * i) * SB + k, SB);
                wmma::load_matrix_sync(al[i], xlo + (m0 + 16 * i) * SB + k, SB);
            }
#pragma unroll
            for (int j = 0; j < 2; j++) {
                wmma::load_matrix_sync(bh[j], whi + (n0 + 16 * j) * SB + k, SB);
                wmma::load_matrix_sync(bl[j], wlo + (n0 + 16 * j) * SB + k, SB);
            }
#pragma unroll
            for (int i = 0; i < 2; i++)
#pragma unroll
                for (int j = 0; j < 2; j++) {
                    wmma::mma_sync(acc[i][j], ah[i], bh[j], acc[i][j]);
                    wmma::mma_sync(acc[i][j], ah[i], bl[j], acc[i][j]);
                    wmma::mma_sync(acc[i][j], al[i], bh[j], acc[i][j]);
                }
        }
        __syncthreads();   // all warps done reading W before TMP overwrite

#pragma unroll
        for (int i = 0; i < 2; i++)
#pragma unroll
            for (int j = 0; j < 2; j++)
                wmma::store_matrix_sync(tmp + (m0 + 16 * i) * SF + (n0 + 16 * j),
                                        acc[i][j], SF, wmma::mem_row_major);
        __syncthreads();

        // convert fp32 TMP -> bf16 hi/lo dst
        {
            const int r = tid >> 2, c0 = (tid & 3) * 32;
#pragma unroll
            for (int jj = 0; jj < 8; jj++) {
                float4 f = *(const float4*)(tmp + r * SF + c0 + jj * 4);
                unsigned h0, l0, h1, l1;
                split2(f.x, f.y, h0, l0);
                split2(f.z, f.w, h1, l1);
                *(uint2*)(sm + DSTH[p] + (r * SB + c0 + jj * 4) * 2) = make_uint2(h0, h1);
                *(uint2*)(sm + DSTL[p] + (r * SB + c0 + jj * 4) * 2) = make_uint2(l0, l1);
            }
        }
        __syncthreads();
    }

    // ---- scores = Q @ K^T (64x64, K=128) ----
    {
        const int sm0 = 16 * (wid & 3);          // 1 m-tile
        const int sn0 = 32 * (wid >> 2);         // 2 n-tiles
        const __nv_bfloat16* qhi = (const __nv_bfloat16*)(sm + QHI);
        const __nv_bfloat16* qlo = (const __nv_bfloat16*)(sm + QLO);
        const __nv_bfloat16* khi = (const __nv_bfloat16*)(sm + KHI);
        const __nv_bfloat16* klo = (const __nv_bfloat16*)(sm + KLO);
        FC acc[2];
        wmma::fill_fragment(acc[0], 0.0f);
        wmma::fill_fragment(acc[1], 0.0f);
#pragma unroll 1
        for (int k = 0; k < 128; k += 16) {
            FA qh, ql;
            FBc kh[2], kl[2];
            wmma::load_matrix_sync(qh, qhi + sm0 * SB + k, SB);
            wmma::load_matrix_sync(ql, qlo + sm0 * SB + k, SB);
#pragma unroll
            for (int j = 0; j < 2; j++) {
                wmma::load_matrix_sync(kh[j], khi + (sn0 + 16 * j) * SB + k, SB);
                wmma::load_matrix_sync(kl[j], klo + (sn0 + 16 * j) * SB + k, SB);
            }
#pragma unroll
            for (int j = 0; j < 2; j++) {
                wmma::mma_sync(acc[j], qh, kh[j], acc[j]);
                wmma::mma_sync(acc[j], qh, kl[j], acc[j]);
                wmma::mma_sync(acc[j], ql, kh[j], acc[j]);
            }
        }
        __syncthreads();   // everyone done with Q/K MMA reads (P will overwrite Q)
#pragma unroll
        for (int j = 0; j < 2; j++)
            wmma::store_matrix_sync(tmp + sm0 * SS + sn0 + 16 * j, acc[j], SS,
                                    wmma::mem_row_major);
        __syncthreads();
    }

    // ---- softmax rows -> P hi/lo (overwrites Q buffer, stride SP) ----
    {
        const int r = tid >> 2, q0 = (tid & 3) * 16;
        float s[16];
#pragma unroll
        for (int j = 0; j < 16; j++) s[j] = tmp[r * SS + q0 + j];
        float mx = s[0];
#pragma unroll
        for (int j = 1; j < 16; j++) mx = fmaxf(mx, s[j]);
        mx = fmaxf(mx, __shfl_xor_sync(0xffffffffu, mx, 1));
        mx = fmaxf(mx, __shfl_xor_sync(0xffffffffu, mx, 2));
        float sum = 0.f;
#pragma unroll
        for (int j = 0; j < 16; j++) { s[j] = __expf(s[j] - mx); sum += s[j]; }
        sum += __shfl_xor_sync(0xffffffffu, sum, 1);
        sum += __shfl_xor_sync(0xffffffffu, sum, 2);
        const float inv = 1.0f / sum;
#pragma unroll
        for (int j = 0; j < 16; j += 2) {
            unsigned h, l;
            split2(s[j] * inv, s[j + 1] * inv, h, l);
            *(unsigned*)(sm + QHI + (r * SP + q0 + j) * 2) = h;
            *(unsigned*)(sm + QLO + (r * SP + q0 + j) * 2) = l;
        }
    }
    __syncthreads();

    // ---- stage Wr (overwrites TMP after softmax consumed it) ----
    stage_W(3);
    __syncthreads();

    // ---- epilogue: acc = P@V  then  acc += X@Wr, relu, store ----
    {
        const __nv_bfloat16* phi = (const __nv_bfloat16*)(sm + QHI);
        const __nv_bfloat16* plo = (const __nv_bfloat16*)(sm + QLO);
        const __nv_bfloat16* vhi = (const __nv_bfloat16*)(sm + VHI);
        const __nv_bfloat16* vlo = (const __nv_bfloat16*)(sm + VLO);
        FC acc[2][2];
#pragma unroll
        for (int i = 0; i < 2; i++)
#pragma unroll
            for (int j = 0; j < 2; j++) wmma::fill_fragment(acc[i][j], 0.0f);

        // P @ V : A=P (row-major, stride SP), B=V (row-major, stride SB), K=64
#pragma unroll 1
        for (int k = 0; k < 64; k += 16) {
            FA ph[2], pl[2];
            FBr vh[2], vl[2];
#pragma unroll
            for (int i = 0; i < 2; i++) {
                wmma::load_matrix_sync(ph[i], phi + (m0 + 16 * i) * SP + k, SP);
                wmma::load_matrix_sync(pl[i], plo + (m0 + 16 * i) * SP + k, SP);
            }
#pragma unroll
            for (int j = 0; j < 2; j++) {
                wmma::load_matrix_sync(vh[j], vhi + k * SB + n0 + 16 * j, SB);
                wmma::load_matrix_sync(vl[j], vlo + k * SB + n0 + 16 * j, SB);
            }
#pragma unroll
            for (int i = 0; i < 2; i++)
#pragma unroll
                for (int j = 0; j < 2; j++) {
                    wmma::mma_sync(acc[i][j], ph[i], vh[j], acc[i][j]);
                    wmma::mma_sync(acc[i][j], ph[i], vl[j], acc[i][j]);
                    wmma::mma_sync(acc[i][j], pl[i], vh[j], acc[i][j]);
                }
        }

        // += X @ Wr : A=X, B=Wr^T col-major, K=128
#pragma unroll 1
        for (int k = 0; k < 128; k += 16) {
            FA ah[2], al[2];
            FBc bh[2], bl[2];
#pragma unroll
            for (int i = 0; i < 2; i++) {
                wmma::load_matrix_sync(ah[i], xhi + (m0 + 16 * i) * SB + k, SB);
                wmma::load_matrix_sync(al[i], xlo + (m0 + 16 * i) * SB + k, SB);
            }
#pragma unroll
            for (int j = 0; j < 2; j++) {
                wmma::load_matrix_sync(bh[j], whi + (n0 + 16 * j) * SB + k, SB);
                wmma::load_matrix_sync(bl[j], wlo + (n0 + 16 * j) * SB + k, SB);
            }
#pragma unroll
            for (int i = 0; i < 2; i++)
#pragma unroll
                for (int j = 0; j < 2; j++) {
                    wmma::mma_sync(acc[i][j], ah[i], bh[j], acc[i][j]);
                    wmma::mma_sync(acc[i][j], ah[i], bl[j], acc[i][j]);
                    wmma::mma_sync(acc[i][j], al[i], bh[j], acc[i][j]);
                }
        }

        float* outp = out + (size_t)b * 8192;
#pragma unroll
        for (int i = 0; i < 2; i++)
#pragma unroll
            for (int j = 0; j < 2; j++) {
#pragma unroll
                for (int e = 0; e < acc[i][j].num_elements; e++)
                    acc[i][j].x[e] = fmaxf(acc[i][j].x[e], 0.0f);
                wmma::store_matrix_sync(outp + (m0 + 16 * i) * 128 + (n0 + 16 * j),
                                        acc[i][j], 128, wmma::mem_row_major);
            }
    }
}

extern "C" void kernel_launch(void* const* d_in, const int* in_sizes, int n_in,
                              void* d_out, int out_size) {
    const float* x  = (const float*)d_in[0];
    const float* Wq = (const float*)d_in[1];
    const float* Wk = (const float*)d_in[2];
    const float* Wv = (const float*)d_in[3];
    const float* Wr = (const float*)d_in[4];
    float* out = (float*)d_out;

    prep_weights<<<256, 256>>>(Wq, Wk, Wv, Wr);
    cudaFuncSetAttribute(autoint_hmma,
                         cudaFuncAttributeMaxDynamicSharedMemorySize, SMEM_BYTES);
    autoint_hmma<<<8192, NT, SMEM_BYTES>>>(x, out);
}